// round 11
// baseline (speedup 1.0000x reference)
#include <cuda_runtime.h>
#include <cuda_bf16.h>

// VanillaRNN diagonal recurrence, f32. MUFU-port-bound (R9: R5/R9 durations
// explained to 2% by max-SM chain count x 8 cyc). Warp-specialized pipe
// split: 2 of the 14 warps on every SMSP run their chains with an all-FMA
// tanh (no MUFU at all); the other 12 stay on tanh.approx. Roles:
// 148 == 1 (mod 7) -> the 7 co-resident blocks of any SM cover all residues
// mod 7, so (bid%7 < 2) picks exactly 2 blocks per SM; in those, warps 4..7
// (one per SMSP) take the FMA role. f16 state fatal (R4); all f32.

#define RB 1024
#define RT 1024
#define RH 256
#define RC 10

__device__ __forceinline__ float tanh_hw(float x) {
    float r;
    asm("tanh.approx.f32 %0, %1;" : "=f"(r) : "f"(x));
    return r;
}

// All-FMA/ALU tanh (R6-validated numerics): deg-5 Taylor 2^r + bit-trick 2^k
// + linear-seed 2-Newton reciprocal. ~17 FMA + 4 ALU ops, |err| ~5e-6 abs.
__device__ __forceinline__ float tanh_fma(float z) {
    const float NL2E2 = -2.885390081777927f;   // -2/ln2
    const float MAGIC = 12582912.0f;           // 1.5 * 2^23
    float az = fminf(fabsf(z), 40.0f);
    float t  = fmaf(az, NL2E2, MAGIC);
    float kf = t - MAGIC;
    float r  = fmaf(az, NL2E2, -kf);
    float sc = __int_as_float((__float_as_int(t) + (127 - 0x4B400000)) << 23);
    float p = 1.33335581464e-3f;
    p = fmaf(p, r, 9.61812910763e-3f);
    p = fmaf(p, r, 5.55041086648e-2f);
    p = fmaf(p, r, 2.40226506959e-1f);
    p = fmaf(p, r, 6.93147180560e-1f);
    p = fmaf(p, r, 1.0f);
    float e   = p * sc;                        // e^{-2|z|}
    float den = e + 1.0f;
    float y  = fmaf(den, -0.5f, 1.45710678f);
    y = y * fmaf(-den, y, 2.0f);
    y = y * fmaf(-den, y, 2.0f);
    float res = fmaf(-(e + e), y, 1.0f);
    return copysignf(res, z);
}

__global__ __launch_bounds__(RH, 7)
void vanilla_rnn_kernel(const float* __restrict__ x,
                        const float* __restrict__ W_hx,
                        const float* __restrict__ W_hh,
                        const float* __restrict__ b_h,
                        const float* __restrict__ W_hp,
                        const float* __restrict__ b_o,
                        float* __restrict__ out)
{
    __shared__ float4 xs4[RT / 4];
    __shared__ float  hs[RH];

    const int b = blockIdx.x;
    const int h = threadIdx.x;

    {
        const float4* xrow = reinterpret_cast<const float4*>(x + (size_t)b * RT);
        xs4[h] = xrow[h];
    }

    const float wi = W_hx[h];
    const float wd = W_hh[h * RH + h];
    const float bh = b_h[h];

    __syncthreads();

    // FMA role: in 2 of every 7 co-resident blocks, warps 4..7 (one per SMSP).
    const bool fma_role = ((b % 7) < 2) && (h >= 128);

    float hv = 0.0f;
    if (fma_role) {
        #pragma unroll 4
        for (int q = 0; q < RT / 4; q++) {
            float4 xv = xs4[q];
            float a0 = fmaf(xv.x, wi, bh);
            float a1 = fmaf(xv.y, wi, bh);
            float a2 = fmaf(xv.z, wi, bh);
            float a3 = fmaf(xv.w, wi, bh);
            hv = tanh_fma(fmaf(hv, wd, a0));
            hv = tanh_fma(fmaf(hv, wd, a1));
            hv = tanh_fma(fmaf(hv, wd, a2));
            hv = tanh_fma(fmaf(hv, wd, a3));
        }
    } else {
        #pragma unroll 4
        for (int q = 0; q < RT / 4; q++) {
            float4 xv = xs4[q];
            float a0 = fmaf(xv.x, wi, bh);
            float a1 = fmaf(xv.y, wi, bh);
            float a2 = fmaf(xv.z, wi, bh);
            float a3 = fmaf(xv.w, wi, bh);
            hv = tanh_hw(fmaf(hv, wd, a0));
            hv = tanh_hw(fmaf(hv, wd, a1));
            hv = tanh_hw(fmaf(hv, wd, a2));
            hv = tanh_hw(fmaf(hv, wd, a3));
        }
    }

    hs[h] = hv;
    __syncthreads();

    if (h < RC) {
        const float* wrow = W_hp + h * RH;
        float acc = b_o[h];
        #pragma unroll 8
        for (int j = 0; j < RH; j++)
            acc = fmaf(hs[j], wrow[j], acc);
        out[b * RC + h] = acc;
    }
}

extern "C" void kernel_launch(void* const* d_in, const int* in_sizes, int n_in,
                              void* d_out, int out_size)
{
    const float* x    = (const float*)d_in[0];
    const float* W_hx = (const float*)d_in[1];
    const float* W_hh = (const float*)d_in[2];
    const float* b_h  = (const float*)d_in[3];
    const float* W_hp = (const float*)d_in[4];
    const float* b_o  = (const float*)d_in[5];
    float* out = (float*)d_out;

    vanilla_rnn_kernel<<<RB, RH>>>(x, W_hx, W_hh, b_h, W_hp, b_o, out);
}